// round 13
// baseline (speedup 1.0000x reference)
#include <cuda_runtime.h>
#include <cstdint>

#define KDIM     256
#define NCOLS    40          // 10 classes * 4 centroids
#define NCLASSES 10
#define KCENT    4
#define NW       10          // warps per CTA
#define BM       (NW * 32)   // 320 rows per CTA tile: each warp 32 rows
#define NTHREADS (NW * 32)   // 320
#define NCHUNK   8           // 8 chunks of K=32
#define STAGES   4           // cp.async pipeline depth (per warp)

// Pre-scattered, normalized, tf32-rounded B fragments.
// float4 index = ((c*5 + nt)*2 + ii)*32 + lane  (lane = g*4 + q), components f,
// holding B_nat[n = nt*8 + g][nat_k = c*32 + 16*ii + 4*q + f]
__device__ float4 g_Bfrag[NCHUNK * 5 * 2 * 32];
// Normalized centroids, natural layout [v][k] (tail kernel).
__device__ float g_centsN[NCOLS * KDIM];

// ---------------------------------------------------------------------------
// Prep: normalize the 40 centroids (x / max(||x||,1e-12)); emit tf32-rounded
// MMA fragments (sector-friendly k-permutation) + natural fp32 copy.
// ---------------------------------------------------------------------------
__global__ void prep_kernel(const float* __restrict__ cents) {
    const int w    = threadIdx.x >> 5;
    const int lane = threadIdx.x & 31;
    float* Bf = reinterpret_cast<float*>(g_Bfrag);
    for (int v = w; v < NCOLS; v += (int)(blockDim.x >> 5)) {
        const float* src = cents + v * KDIM;
        float vals[8];
        float s = 0.f;
        #pragma unroll
        for (int i = 0; i < 8; i++) {
            vals[i] = src[lane + 32 * i];
            s += vals[i] * vals[i];
        }
        #pragma unroll
        for (int off = 16; off; off >>= 1)
            s += __shfl_xor_sync(0xffffffffu, s, off);
        const float inv = 1.f / fmaxf(sqrtf(s), 1e-12f);
        const int nt = v >> 3;
        const int g  = v & 7;
        #pragma unroll
        for (int i = 0; i < 8; i++) {
            const int k = lane + 32 * i;
            const float x = vals[i] * inv;
            g_centsN[v * KDIM + k] = x;
            uint32_t u;
            asm("cvt.rna.tf32.f32 %0, %1;" : "=r"(u) : "f"(x));
            const int c   = k >> 5;
            const int w32 = k & 31;
            const int ii  = w32 >> 4;
            const int q   = (w32 >> 2) & 3;
            const int f   = w32 & 3;
            Bf[((((c * 5 + nt) * 2 + ii) * 32) + (g * 4 + q)) * 4 + f] =
                __uint_as_float(u);
        }
    }
}

__device__ __forceinline__ void cp16(uint32_t dst, const float* src) {
    asm volatile("cp.async.cg.shared.global [%0], [%1], 16;"
                 :: "r"(dst), "l"(src) : "memory");
}
__device__ __forceinline__ void cp_commit() {
    asm volatile("cp.async.commit_group;" ::: "memory");
}
__device__ __forceinline__ void cp_wait3() {
    asm volatile("cp.async.wait_group 3;" ::: "memory");
}

// ---------------------------------------------------------------------------
// Hot kernel: persistent CTAs (1/SM), 10 warps (2-3 per SMSP), warp-private
// depth-4 cp.async pipeline for A, B conflict-free LDS.128 from smem,
// mma m16n8k8 tf32, fused 1 - max_k epilogue.
// smem: A 10 warps * 4 stages * 4KB = 160KB + B 40KB = 200KB.
// ---------------------------------------------------------------------------
extern __shared__ float4 smem4[];

__global__ void __launch_bounds__(NTHREADS, 1)
gemm_kernel(const float* __restrict__ codes, float* __restrict__ out,
            int ntiles) {
    float4* const Asm = smem4;                          // 10240 float4 (160 KB)
    float4* const Bsm = smem4 + NW * STAGES * 8 * 32;   // 2560 float4 (40 KB)

    const int tid  = threadIdx.x;
    const int lane = tid & 31;
    const int warp = tid >> 5;
    const int g = lane >> 2;     // 0..7
    const int q = lane & 3;      // 0..3
    const int b = blockIdx.x;
    const int G = gridDim.x;

    const int myn = (ntiles > b) ? ((ntiles - b - 1) / G + 1) : 0;
    if (myn == 0) return;                  // uniform per CTA
    const int total = myn * NCHUNK;

    // byte address of this thread's slot in stage 0 of its warp region
    const uint32_t abase =
        (uint32_t)__cvta_generic_to_shared(Asm) +
        ((uint32_t)(warp * STAGES) * 8 * 32 + lane) * 16u;

    // Issue all 8 cp.asyncs for flat chunk fc (clamped at drain), 1 group.
    auto issue = [&](int fc) {
        fc = fc < total - 1 ? fc : total - 1;
        const int st = fc & (STAGES - 1);
        const long rowb = (long)(b + (fc >> 3) * G) * BM + warp * 32 + g;
        const float* ap = codes + rowb * KDIM + (fc & 7) * 32 + 4 * q;
        const uint32_t dst = abase + (uint32_t)st * (8 * 32 * 16);
        #pragma unroll
        for (int j = 0; j < 4; j++)
            #pragma unroll
            for (int i = 0; i < 2; i++)
                cp16(dst + (uint32_t)((j * 2 + i) * 32) * 16,
                     ap + j * 8 * KDIM + i * 16);
        cp_commit();
    };

    // Prologue: start the pipeline before anything else touches memory.
    issue(0); issue(1); issue(2);

    // Stage B fragments (once per CTA, persistent).
    for (int i = tid; i < 2560; i += NTHREADS)
        Bsm[i] = g_Bfrag[i];
    __syncthreads();

    const float4* const aread = Asm + (warp * STAGES) * 8 * 32 + lane;

    for (int ti = 0; ti < myn; ti++) {
        float acc[2][5][4];
        #pragma unroll
        for (int t = 0; t < 2; t++)
            #pragma unroll
            for (int n = 0; n < 5; n++)
                #pragma unroll
                for (int j = 0; j < 4; j++) acc[t][n][j] = 0.f;

        #pragma unroll
        for (int c = 0; c < NCHUNK; c++) {
            const int fc = ti * NCHUNK + c;
            issue(fc + 3);
            cp_wait3();                    // chunk fc complete
            const int st = fc & (STAGES - 1);

            float4 A4[4][2];
            #pragma unroll
            for (int j = 0; j < 4; j++)
                #pragma unroll
                for (int i = 0; i < 2; i++)
                    A4[j][i] = aread[(st * 8 + j * 2 + i) * 32];

            #pragma unroll
            for (int nt = 0; nt < 5; nt++) {
                const float4 wb0 = Bsm[((c * 5 + nt) * 2 + 0) * 32 + lane];
                const float4 wb1 = Bsm[((c * 5 + nt) * 2 + 1) * 32 + lane];
                #pragma unroll
                for (int m = 0; m < 4; m++) {
                    const float4 wb = (m < 2) ? wb0 : wb1;
                    const uint32_t b0 = __float_as_uint((m & 1) ? wb.z : wb.x);
                    const uint32_t b1 = __float_as_uint((m & 1) ? wb.w : wb.y);
                    #pragma unroll
                    for (int t = 0; t < 2; t++) {
                        const float4 p0 = A4[2 * t][m >> 1];
                        const float4 p1 = A4[2 * t + 1][m >> 1];
                        const uint32_t a0 = __float_as_uint((m & 1) ? p0.z : p0.x);
                        const uint32_t a1 = __float_as_uint((m & 1) ? p1.z : p1.x);
                        const uint32_t a2 = __float_as_uint((m & 1) ? p0.w : p0.y);
                        const uint32_t a3 = __float_as_uint((m & 1) ? p1.w : p1.y);
                        asm volatile(
                            "mma.sync.aligned.m16n8k8.row.col.f32.tf32.tf32.f32 "
                            "{%0,%1,%2,%3}, {%4,%5,%6,%7}, {%8,%9}, {%0,%1,%2,%3};"
                            : "+f"(acc[t][nt][0]), "+f"(acc[t][nt][1]),
                              "+f"(acc[t][nt][2]), "+f"(acc[t][nt][3])
                            : "r"(a0), "r"(a1), "r"(a2), "r"(a3),
                              "r"(b0), "r"(b1));
                    }
                }
            }
        }

        // Epilogue for this tile.
        const long row0 = (long)(b + ti * G) * BM + warp * 32 + g;
        float* const obase = out + row0 * NCLASSES;
        #pragma unroll
        for (int t = 0; t < 2; t++) {
            #pragma unroll
            for (int nt = 0; nt < 5; nt++) {
                float m0 = fmaxf(acc[t][nt][0], acc[t][nt][1]);
                float m1 = fmaxf(acc[t][nt][2], acc[t][nt][3]);
                m0 = fmaxf(m0, __shfl_xor_sync(0xffffffffu, m0, 1));
                m1 = fmaxf(m1, __shfl_xor_sync(0xffffffffu, m1, 1));
                const int cls = nt * 2 + (q >> 1);
                if ((q & 1) == 0) {
                    __stcs(obase + (16 * t) * NCLASSES + cls, 1.f - m0);
                    __stcs(obase + (16 * t + 8) * NCLASSES + cls, 1.f - m1);
                }
            }
        }
    }
}

// ---------------------------------------------------------------------------
// Tail: remaining (< BM) rows, plain fp32.
// ---------------------------------------------------------------------------
__global__ void tail_kernel(const float* __restrict__ codes,
                            float* __restrict__ out,
                            long rbase, int nrows) {
    const long row = rbase + blockIdx.x * blockDim.x + threadIdx.x;
    if (row >= nrows) return;
    const float* a = codes + row * KDIM;
    float best[NCLASSES];
    #pragma unroll
    for (int c = 0; c < NCLASSES; c++) best[c] = -1e30f;
    for (int v = 0; v < NCOLS; v++) {
        const float* bp = g_centsN + v * KDIM;
        float s = 0.f;
        for (int k = 0; k < KDIM; k++) s += a[k] * bp[k];
        const int c = v / KCENT;
        best[c] = fmaxf(best[c], s);
    }
    #pragma unroll
    for (int c = 0; c < NCLASSES; c++)
        out[row * NCLASSES + c] = 1.f - best[c];
}

// ---------------------------------------------------------------------------
extern "C" void kernel_launch(void* const* d_in, const int* in_sizes, int n_in,
                              void* d_out, int out_size) {
    const float* codes = (const float*)d_in[0];   // (B, 256) f32
    const float* cents = (const float*)d_in[1];   // (10, 4, 256) f32
    float* out = (float*)d_out;                   // (B, 10) f32

    const int nrows  = in_sizes[0] / KDIM;
    const int ntiles = nrows / BM;
    const int tail   = nrows - ntiles * BM;

    const int smem_bytes = (NW * STAGES * 8 * 32 + 2560) * (int)sizeof(float4);

    cudaFuncSetAttribute(gemm_kernel,
                         cudaFuncAttributeMaxDynamicSharedMemorySize,
                         smem_bytes);

    int nsm = 0;
    cudaDeviceGetAttribute(&nsm, cudaDevAttrMultiProcessorCount, 0);
    if (nsm <= 0) nsm = 148;

    prep_kernel<<<1, 256>>>(cents);

    if (ntiles > 0) {
        const int grid = ntiles < nsm ? ntiles : nsm;
        gemm_kernel<<<grid, NTHREADS, smem_bytes>>>(codes, out, ntiles);
    }
    if (tail > 0) {
        const int tb = (tail + 255) / 256;
        tail_kernel<<<tb, 256>>>(codes, out, (long)ntiles * BM, nrows);
    }
}

// round 14
// speedup vs baseline: 8.1895x; 8.1895x over previous
#include <cuda_runtime.h>
#include <cstdint>

#define KDIM     256
#define NCOLS    40          // 10 classes * 4 centroids
#define NCLASSES 10
#define KCENT    4
#define BM       256         // rows per CTA tile: 8 warps x 32 rows
#define NTHREADS 256
#define NCHUNK   8           // 8 chunks of K=32
#define STAGES   4           // cp.async pipeline depth (per warp)

__device__ __forceinline__ void cp16(uint32_t dst, const float* src) {
    asm volatile("cp.async.cg.shared.global [%0], [%1], 16;"
                 :: "r"(dst), "l"(src) : "memory");
}
__device__ __forceinline__ void cp_commit() {
    asm volatile("cp.async.commit_group;" ::: "memory");
}
__device__ __forceinline__ void cp_wait3() {
    asm volatile("cp.async.wait_group 3;" ::: "memory");
}

// ---------------------------------------------------------------------------
// Hot kernel: persistent CTAs (1/SM), 8 warps. Warp-private depth-4 cp.async
// pipeline for A; B fragments computed IN-CTA (normalize + tf32 round +
// scatter) overlapped with the A prologue; B conflict-free LDS.128;
// mma m16n8k8 tf32; fused 1 - max_k epilogue.
// smem: A 8 warps * 4 stages * 4KB = 128KB + B 40KB = 168KB.
// Bsm float4 index = ((c*5 + nt)*2 + ii)*32 + (g*4+q), component f, holding
// B_nat[n = nt*8 + g][nat_k = c*32 + 16*ii + 4*q + f].
// ---------------------------------------------------------------------------
extern __shared__ float4 smem4[];

__global__ void __launch_bounds__(NTHREADS, 1)
gemm_kernel(const float* __restrict__ codes,
            const float* __restrict__ cents,
            float* __restrict__ out, int ntiles) {
    float4* const Asm = smem4;            // 8192 float4 (128 KB)
    float4* const Bsm = smem4 + 8192;     // 2560 float4 (40 KB)

    const int tid  = threadIdx.x;
    const int lane = tid & 31;
    const int warp = tid >> 5;
    const int g = lane >> 2;     // 0..7
    const int q = lane & 3;      // 0..3
    const int b = blockIdx.x;
    const int G = gridDim.x;

    const int myn = (ntiles > b) ? ((ntiles - b - 1) / G + 1) : 0;
    if (myn == 0) return;                  // uniform per CTA
    const int total = myn * NCHUNK;

    // byte address of this thread's slot in stage 0 of its warp region
    const uint32_t abase =
        (uint32_t)__cvta_generic_to_shared(Asm) +
        ((uint32_t)(warp * STAGES) * 8 * 32 + lane) * 16u;

    // Issue all 8 cp.asyncs for flat chunk fc (clamped at drain), 1 group.
    auto issue = [&](int fc) {
        fc = fc < total - 1 ? fc : total - 1;
        const int st = fc & (STAGES - 1);
        const long rowb = (long)(b + (fc >> 3) * G) * BM + warp * 32 + g;
        const float* ap = codes + rowb * KDIM + (fc & 7) * 32 + 4 * q;
        const uint32_t dst = abase + (uint32_t)st * (8 * 32 * 16);
        #pragma unroll
        for (int j = 0; j < 4; j++)
            #pragma unroll
            for (int i = 0; i < 2; i++)
                cp16(dst + (uint32_t)((j * 2 + i) * 32) * 16,
                     ap + j * 8 * KDIM + i * 16);
        cp_commit();
    };

    // Prologue: start the A pipeline before anything else touches memory.
    issue(0); issue(1); issue(2);

    // In-CTA B prep (overlapped with the A prologue): warp w owns vectors
    // v = 5w .. 5w+4. Arithmetic identical to the old prep_kernel.
    {
        float* const Bf = reinterpret_cast<float*>(Bsm);
        #pragma unroll
        for (int vv = 0; vv < 5; vv++) {
            const int v = warp * 5 + vv;
            const float* src = cents + v * KDIM;
            float vals[8];
            float s = 0.f;
            #pragma unroll
            for (int i = 0; i < 8; i++) {
                vals[i] = src[lane + 32 * i];
                s += vals[i] * vals[i];
            }
            #pragma unroll
            for (int off = 16; off; off >>= 1)
                s += __shfl_xor_sync(0xffffffffu, s, off);
            const float inv = 1.f / fmaxf(sqrtf(s), 1e-12f);
            const int nt = v >> 3;
            const int gg = v & 7;
            #pragma unroll
            for (int i = 0; i < 8; i++) {
                const int k = lane + 32 * i;
                const float x = vals[i] * inv;
                uint32_t u;
                asm("cvt.rna.tf32.f32 %0, %1;" : "=r"(u) : "f"(x));
                const int c   = k >> 5;
                const int w32 = k & 31;
                const int ii  = w32 >> 4;
                const int qq  = (w32 >> 2) & 3;
                const int f   = w32 & 3;
                Bf[((((c * 5 + nt) * 2 + ii) * 32) + (gg * 4 + qq)) * 4 + f] =
                    __uint_as_float(u);
            }
        }
    }
    __syncthreads();

    const float4* const aread = Asm + (warp * STAGES) * 8 * 32 + lane;

    for (int ti = 0; ti < myn; ti++) {
        float acc[2][5][4];
        #pragma unroll
        for (int t = 0; t < 2; t++)
            #pragma unroll
            for (int n = 0; n < 5; n++)
                #pragma unroll
                for (int j = 0; j < 4; j++) acc[t][n][j] = 0.f;

        #pragma unroll
        for (int c = 0; c < NCHUNK; c++) {
            const int fc = ti * NCHUNK + c;
            issue(fc + 3);
            cp_wait3();                    // chunk fc complete
            const int st = fc & (STAGES - 1);

            float4 A4[4][2];
            #pragma unroll
            for (int j = 0; j < 4; j++)
                #pragma unroll
                for (int i = 0; i < 2; i++)
                    A4[j][i] = aread[(st * 8 + j * 2 + i) * 32];

            #pragma unroll
            for (int nt = 0; nt < 5; nt++) {
                const float4 wb0 = Bsm[((c * 5 + nt) * 2 + 0) * 32 + lane];
                const float4 wb1 = Bsm[((c * 5 + nt) * 2 + 1) * 32 + lane];
                #pragma unroll
                for (int m = 0; m < 4; m++) {
                    const float4 wb = (m < 2) ? wb0 : wb1;
                    const uint32_t b0 = __float_as_uint((m & 1) ? wb.z : wb.x);
                    const uint32_t b1 = __float_as_uint((m & 1) ? wb.w : wb.y);
                    #pragma unroll
                    for (int t = 0; t < 2; t++) {
                        const float4 p0 = A4[2 * t][m >> 1];
                        const float4 p1 = A4[2 * t + 1][m >> 1];
                        const uint32_t a0 = __float_as_uint((m & 1) ? p0.z : p0.x);
                        const uint32_t a1 = __float_as_uint((m & 1) ? p1.z : p1.x);
                        const uint32_t a2 = __float_as_uint((m & 1) ? p0.w : p0.y);
                        const uint32_t a3 = __float_as_uint((m & 1) ? p1.w : p1.y);
                        asm volatile(
                            "mma.sync.aligned.m16n8k8.row.col.f32.tf32.tf32.f32 "
                            "{%0,%1,%2,%3}, {%4,%5,%6,%7}, {%8,%9}, {%0,%1,%2,%3};"
                            : "+f"(acc[t][nt][0]), "+f"(acc[t][nt][1]),
                              "+f"(acc[t][nt][2]), "+f"(acc[t][nt][3])
                            : "r"(a0), "r"(a1), "r"(a2), "r"(a3),
                              "r"(b0), "r"(b1));
                    }
                }
            }
        }

        // Epilogue for this tile.
        const long row0 = (long)(b + ti * G) * BM + warp * 32 + g;
        float* const obase = out + row0 * NCLASSES;
        #pragma unroll
        for (int t = 0; t < 2; t++) {
            #pragma unroll
            for (int nt = 0; nt < 5; nt++) {
                float m0 = fmaxf(acc[t][nt][0], acc[t][nt][1]);
                float m1 = fmaxf(acc[t][nt][2], acc[t][nt][3]);
                m0 = fmaxf(m0, __shfl_xor_sync(0xffffffffu, m0, 1));
                m1 = fmaxf(m1, __shfl_xor_sync(0xffffffffu, m1, 1));
                const int cls = nt * 2 + (q >> 1);
                if ((q & 1) == 0) {
                    __stcs(obase + (16 * t) * NCLASSES + cls, 1.f - m0);
                    __stcs(obase + (16 * t + 8) * NCLASSES + cls, 1.f - m1);
                }
            }
        }
    }
}

// ---------------------------------------------------------------------------
// Tail: remaining (< BM) rows, plain fp32, self-contained (normalizes the
// centroids on the fly). Never launched when nrows % 256 == 0.
// ---------------------------------------------------------------------------
__global__ void tail_kernel(const float* __restrict__ codes,
                            const float* __restrict__ cents,
                            float* __restrict__ out,
                            long rbase, int nrows) {
    const long row = rbase + blockIdx.x * blockDim.x + threadIdx.x;
    if (row >= nrows) return;
    const float* a = codes + row * KDIM;
    float best[NCLASSES];
    #pragma unroll
    for (int c = 0; c < NCLASSES; c++) best[c] = -1e30f;
    for (int v = 0; v < NCOLS; v++) {
        const float* bp = cents + v * KDIM;
        float nrm = 0.f, s = 0.f;
        for (int k = 0; k < KDIM; k++) {
            nrm += bp[k] * bp[k];
            s   += a[k] * bp[k];
        }
        s *= 1.f / fmaxf(sqrtf(nrm), 1e-12f);
        const int c = v / KCENT;
        best[c] = fmaxf(best[c], s);
    }
    #pragma unroll
    for (int c = 0; c < NCLASSES; c++)
        out[row * NCLASSES + c] = 1.f - best[c];
}

// ---------------------------------------------------------------------------
extern "C" void kernel_launch(void* const* d_in, const int* in_sizes, int n_in,
                              void* d_out, int out_size) {
    const float* codes = (const float*)d_in[0];   // (B, 256) f32
    const float* cents = (const float*)d_in[1];   // (10, 4, 256) f32
    float* out = (float*)d_out;                   // (B, 10) f32

    const int nrows  = in_sizes[0] / KDIM;
    const int ntiles = nrows / BM;
    const int tail   = nrows - ntiles * BM;

    const int smem_bytes = (8192 + 2560) * (int)sizeof(float4);  // 172032

    cudaFuncSetAttribute(gemm_kernel,
                         cudaFuncAttributeMaxDynamicSharedMemorySize,
                         smem_bytes);

    int nsm = 0;
    cudaDeviceGetAttribute(&nsm, cudaDevAttrMultiProcessorCount, 0);
    if (nsm <= 0) nsm = 148;

    if (ntiles > 0) {
        const int grid = ntiles < nsm ? ntiles : nsm;
        gemm_kernel<<<grid, NTHREADS, smem_bytes>>>(codes, cents, out, ntiles);
    }
    if (tail > 0) {
        const int tb = (tail + 255) / 256;
        tail_kernel<<<tb, 256>>>(codes, cents, out, (long)ntiles * BM, nrows);
    }
}

// round 15
// speedup vs baseline: 8.5764x; 1.0472x over previous
#include <cuda_runtime.h>
#include <cstdint>

#define KDIM     256
#define NCOLS    40          // 10 classes * 4 centroids
#define NCLASSES 10
#define KCENT    4
#define BM       256         // rows per CTA tile: 8 warps x 32 rows
#define NTHREADS 256
#define NCHUNK   8           // 8 chunks of K=32
#define STAGES   4           // cp.async pipeline depth (per warp)

__device__ __forceinline__ void cp16(uint32_t dst, const float* src) {
    asm volatile("cp.async.cg.shared.global [%0], [%1], 16;"
                 :: "r"(dst), "l"(src) : "memory");
}
__device__ __forceinline__ void cp_commit() {
    asm volatile("cp.async.commit_group;" ::: "memory");
}
__device__ __forceinline__ void cp_wait3() {
    asm volatile("cp.async.wait_group 3;" ::: "memory");
}
__device__ __forceinline__ float tf32r(float x) {
    uint32_t u;
    asm("cvt.rna.tf32.f32 %0, %1;" : "=r"(u) : "f"(x));
    return __uint_as_float(u);
}

// ---------------------------------------------------------------------------
// Hot kernel: persistent CTAs (1/SM), 8 warps (R8 geometry, unchanged loop).
// Warp-private depth-4 cp.async pipeline for A (uint32 addressing);
// B fragments computed IN-CTA with a short chain (2xLDG.128 -> reduce ->
// 2xSTS.128 per vector), overlapped with the A prologue.
// B conflict-free LDS.128; mma m16n8k8 tf32; fused 1 - max_k epilogue.
// smem: A 8 warps * 4 stages * 4KB = 128KB + B 40KB = 168KB.
// Bsm float4 index = ((c*5 + nt)*2 + ii)*32 + (g*4+q), component f, holding
// B_nat[n = nt*8 + g][nat_k = c*32 + 16*ii + 4*q + f].
// ---------------------------------------------------------------------------
extern __shared__ float4 smem4[];

__global__ void __launch_bounds__(NTHREADS, 1)
gemm_kernel(const float* __restrict__ codes,
            const float* __restrict__ cents,
            float* __restrict__ out, int ntiles) {
    float4* const Asm = smem4;            // 8192 float4 (128 KB)
    float4* const Bsm = smem4 + 8192;     // 2560 float4 (40 KB)

    const int tid  = threadIdx.x;
    const int lane = tid & 31;
    const int warp = tid >> 5;
    const int g = lane >> 2;     // 0..7
    const int q = lane & 3;      // 0..3
    const int b = blockIdx.x;
    const int G = gridDim.x;

    const int myn = (ntiles > b) ? ((ntiles - b - 1) / G + 1) : 0;
    if (myn == 0) return;                  // uniform per CTA
    const int total = myn * NCHUNK;

    // byte address of this thread's slot in stage 0 of its warp region
    const uint32_t abase =
        (uint32_t)__cvta_generic_to_shared(Asm) +
        ((uint32_t)(warp * STAGES) * 8 * 32 + lane) * 16u;

    // 32-bit element-offset addressing (max offset 268M < 2^32)
    const uint32_t boff0   = ((uint32_t)b * BM + (uint32_t)(warp * 32 + g)) * KDIM
                           + (uint32_t)(4 * q);
    const uint32_t gstride = (uint32_t)G * BM * KDIM;

    // Issue all 8 cp.asyncs for flat chunk fc (clamped at drain), 1 group.
    auto issue = [&](int fc) {
        fc = fc < total - 1 ? fc : total - 1;
        const int st = fc & (STAGES - 1);
        const float* ap = codes + (boff0 + (uint32_t)(fc >> 3) * gstride
                                   + (uint32_t)((fc & 7) * 32));
        const uint32_t dst = abase + (uint32_t)st * (8 * 32 * 16);
        #pragma unroll
        for (int j = 0; j < 4; j++)
            #pragma unroll
            for (int i = 0; i < 2; i++)
                cp16(dst + (uint32_t)((j * 2 + i) * 32) * 16,
                     ap + j * 8 * KDIM + i * 16);
        cp_commit();
    };

    // Prologue: start the A pipeline before anything else touches memory.
    issue(0); issue(1); issue(2);

    // In-CTA B prep, short chain: warp w owns vectors v = 5w .. 5w+4.
    // For k = 4*lane + f:  slot = (((lane>>3)*5+nt)*2 + ((lane>>2)&1))*32
    //                             + gg*4 + (lane&3), components == f.
    // For k+128: c shifts by +4.
    {
        const int sl  = (lane >> 3) * 5;        // c for v0 part, *5
        const int ii  = (lane >> 2) & 1;
        const int col = (lane & 3);
        #pragma unroll
        for (int vv = 0; vv < 5; vv++) {
            const int v = warp * 5 + vv;
            const float4* src4 = reinterpret_cast<const float4*>(cents + v * KDIM);
            const float4 v0 = src4[lane];
            const float4 v1 = src4[lane + 32];
            float s = v0.x * v0.x + v0.y * v0.y + v0.z * v0.z + v0.w * v0.w
                    + v1.x * v1.x + v1.y * v1.y + v1.z * v1.z + v1.w * v1.w;
            #pragma unroll
            for (int off = 16; off; off >>= 1)
                s += __shfl_xor_sync(0xffffffffu, s, off);
            const float inv = 1.f / fmaxf(sqrtf(s), 1e-12f);
            const int nt = v >> 3;
            const int gg = v & 7;
            float4 o0, o1;
            o0.x = tf32r(v0.x * inv); o0.y = tf32r(v0.y * inv);
            o0.z = tf32r(v0.z * inv); o0.w = tf32r(v0.w * inv);
            o1.x = tf32r(v1.x * inv); o1.y = tf32r(v1.y * inv);
            o1.z = tf32r(v1.z * inv); o1.w = tf32r(v1.w * inv);
            Bsm[((sl + nt) * 2 + ii) * 32 + gg * 4 + col] = o0;          // c
            Bsm[((sl + 20 + nt) * 2 + ii) * 32 + gg * 4 + col] = o1;     // c+4
        }
    }
    __syncthreads();

    const float4* const aread = Asm + (warp * STAGES) * 8 * 32 + lane;

    for (int ti = 0; ti < myn; ti++) {
        float acc[2][5][4];
        #pragma unroll
        for (int t = 0; t < 2; t++)
            #pragma unroll
            for (int n = 0; n < 5; n++)
                #pragma unroll
                for (int j = 0; j < 4; j++) acc[t][n][j] = 0.f;

        #pragma unroll
        for (int c = 0; c < NCHUNK; c++) {
            const int fc = ti * NCHUNK + c;
            issue(fc + 3);
            cp_wait3();                    // chunk fc complete
            const int st = fc & (STAGES - 1);

            float4 A4[4][2];
            #pragma unroll
            for (int j = 0; j < 4; j++)
                #pragma unroll
                for (int i = 0; i < 2; i++)
                    A4[j][i] = aread[(st * 8 + j * 2 + i) * 32];

            #pragma unroll
            for (int nt = 0; nt < 5; nt++) {
                const float4 wb0 = Bsm[((c * 5 + nt) * 2 + 0) * 32 + lane];
                const float4 wb1 = Bsm[((c * 5 + nt) * 2 + 1) * 32 + lane];
                #pragma unroll
                for (int m = 0; m < 4; m++) {
                    const float4 wb = (m < 2) ? wb0 : wb1;
                    const uint32_t b0 = __float_as_uint((m & 1) ? wb.z : wb.x);
                    const uint32_t b1 = __float_as_uint((m & 1) ? wb.w : wb.y);
                    #pragma unroll
                    for (int t = 0; t < 2; t++) {
                        const float4 p0 = A4[2 * t][m >> 1];
                        const float4 p1 = A4[2 * t + 1][m >> 1];
                        const uint32_t a0 = __float_as_uint((m & 1) ? p0.z : p0.x);
                        const uint32_t a1 = __float_as_uint((m & 1) ? p1.z : p1.x);
                        const uint32_t a2 = __float_as_uint((m & 1) ? p0.w : p0.y);
                        const uint32_t a3 = __float_as_uint((m & 1) ? p1.w : p1.y);
                        asm volatile(
                            "mma.sync.aligned.m16n8k8.row.col.f32.tf32.tf32.f32 "
                            "{%0,%1,%2,%3}, {%4,%5,%6,%7}, {%8,%9}, {%0,%1,%2,%3};"
                            : "+f"(acc[t][nt][0]), "+f"(acc[t][nt][1]),
                              "+f"(acc[t][nt][2]), "+f"(acc[t][nt][3])
                            : "r"(a0), "r"(a1), "r"(a2), "r"(a3),
                              "r"(b0), "r"(b1));
                    }
                }
            }
        }

        // Epilogue for this tile.
        const long row0 = (long)(b + ti * G) * BM + warp * 32 + g;
        float* const obase = out + row0 * NCLASSES;
        #pragma unroll
        for (int t = 0; t < 2; t++) {
            #pragma unroll
            for (int nt = 0; nt < 5; nt++) {
                float m0 = fmaxf(acc[t][nt][0], acc[t][nt][1]);
                float m1 = fmaxf(acc[t][nt][2], acc[t][nt][3]);
                m0 = fmaxf(m0, __shfl_xor_sync(0xffffffffu, m0, 1));
                m1 = fmaxf(m1, __shfl_xor_sync(0xffffffffu, m1, 1));
                const int cls = nt * 2 + (q >> 1);
                if ((q & 1) == 0) {
                    __stcs(obase + (16 * t) * NCLASSES + cls, 1.f - m0);
                    __stcs(obase + (16 * t + 8) * NCLASSES + cls, 1.f - m1);
                }
            }
        }
    }
}

// ---------------------------------------------------------------------------
// Tail: remaining (< BM) rows, plain fp32, self-contained (normalizes the
// centroids on the fly). Never launched when nrows % 256 == 0.
// ---------------------------------------------------------------------------
__global__ void tail_kernel(const float* __restrict__ codes,
                            const float* __restrict__ cents,
                            float* __restrict__ out,
                            long rbase, int nrows) {
    const long row = rbase + blockIdx.x * blockDim.x + threadIdx.x;
    if (row >= nrows) return;
    const float* a = codes + row * KDIM;
    float best[NCLASSES];
    #pragma unroll
    for (int c = 0; c < NCLASSES; c++) best[c] = -1e30f;
    for (int v = 0; v < NCOLS; v++) {
        const float* bp = cents + v * KDIM;
        float nrm = 0.f, s = 0.f;
        for (int k = 0; k < KDIM; k++) {
            nrm += bp[k] * bp[k];
            s   += a[k] * bp[k];
        }
        s *= 1.f / fmaxf(sqrtf(nrm), 1e-12f);
        const int c = v / KCENT;
        best[c] = fmaxf(best[c], s);
    }
    #pragma unroll
    for (int c = 0; c < NCLASSES; c++)
        out[row * NCLASSES + c] = 1.f - best[c];
}

// ---------------------------------------------------------------------------
extern "C" void kernel_launch(void* const* d_in, const int* in_sizes, int n_in,
                              void* d_out, int out_size) {
    const float* codes = (const float*)d_in[0];   // (B, 256) f32
    const float* cents = (const float*)d_in[1];   // (10, 4, 256) f32
    float* out = (float*)d_out;                   // (B, 10) f32

    const int nrows  = in_sizes[0] / KDIM;
    const int ntiles = nrows / BM;
    const int tail   = nrows - ntiles * BM;

    const int smem_bytes = (8192 + 2560) * (int)sizeof(float4);  // 172032

    cudaFuncSetAttribute(gemm_kernel,
                         cudaFuncAttributeMaxDynamicSharedMemorySize,
                         smem_bytes);

    int nsm = 0;
    cudaDeviceGetAttribute(&nsm, cudaDevAttrMultiProcessorCount, 0);
    if (nsm <= 0) nsm = 148;

    if (ntiles > 0) {
        const int grid = ntiles < nsm ? ntiles : nsm;
        gemm_kernel<<<grid, NTHREADS, smem_bytes>>>(codes, cents, out, ntiles);
    }
    if (tail > 0) {
        const int tb = (tail + 255) / 256;
        tail_kernel<<<tb, 256>>>(codes, cents, out, (long)ntiles * BM, nrows);
    }
}